// round 14
// baseline (speedup 1.0000x reference)
#include <cuda_runtime.h>
#include <cuda_fp16.h>
#include <math.h>
#include <stdint.h>

#define BB 16
#define TT 1025
#define DD 1024
#define EE 8
#define RR 128
#define CC 192
#define N1 1536            // EE*CC
#define NTOK 16384         // BB*(TT-1)
#define NTOT (16*1025*1024)

// -------- scratch (static device arrays; no allocations) --------
__device__ float g_probs[NTOK * EE];
__device__ __half g_xth[(size_t)NTOK * DD];                    // fp16 compact h
__device__ __half g_midh[(size_t)NTOK * N1];                   // fp16 mid
__device__ uint32_t g_wdt2[(size_t)(DD / 2) * N1];             // half2 [k/2][n]
__device__ uint32_t g_wut2[(size_t)(N1 / 2) * DD];             // half2 [k/2][d]
__device__ uint32_t g_qt2[(size_t)(DD / 2) * RR];              // half2 [k/2][r]
__device__ double g_ortho;
__device__ double g_ent;

// -------- helpers --------
__device__ __forceinline__ void mma_f16(float* c,
                                        uint32_t a0, uint32_t a1, uint32_t a2, uint32_t a3,
                                        uint32_t b0, uint32_t b1) {
    asm volatile("mma.sync.aligned.m16n8k16.row.col.f32.f16.f16.f32 "
                 "{%0,%1,%2,%3}, {%4,%5,%6,%7}, {%8,%9}, {%0,%1,%2,%3};"
                 : "+f"(c[0]), "+f"(c[1]), "+f"(c[2]), "+f"(c[3])
                 : "r"(a0), "r"(a1), "r"(a2), "r"(a3), "r"(b0), "r"(b1));
}
__device__ __forceinline__ void cp_async16(void* smem, const void* gmem) {
    uint32_t s = (uint32_t)__cvta_generic_to_shared(smem);
    asm volatile("cp.async.cg.shared.global [%0], [%1], 16;\n" :: "r"(s), "l"(gmem));
}
#define CP_COMMIT() asm volatile("cp.async.commit_group;\n" ::: "memory")
#define CP_WAIT1()  asm volatile("cp.async.wait_group 1;\n" ::: "memory")
#define CP_WAIT0()  asm volatile("cp.async.wait_group 0;\n" ::: "memory")

// GEMM SMEM geometry (BK=64): A [128][72] halves, B [32][136] half2
#define ASH_STRIDE 72
#define ASH_BUF (128 * ASH_STRIDE)          // 9216 halves / buffer
#define BS2_STRIDE 136
#define BS2_BUF (32 * BS2_STRIDE)           // 4352 u32 / buffer
#define GEMM_DYN_SMEM (2 * ASH_BUF * 2 + 2 * BS2_BUF * 4)      // 71680 B
// Router geometry (BK=32, R11 proven): A [128][40] halves, B [16][136] half2
#define RA_STRIDE 40
#define RA_BUF (128 * RA_STRIDE)
#define RB_BUF (16 * 136)
#define RZS 129
#define ROUTER_DYN_SMEM ((128 * RZS + EE * RZS) * 4)           // 70176 B

// ---------------- init ----------------
__global__ void init_kernel(const float* __restrict__ x, float* __restrict__ out) {
    int i = blockIdx.x * blockDim.x + threadIdx.x;
    int nvec = BB * DD / 4;
    if (i < nvec) {
        int b = i / (DD / 4);
        int d4 = i % (DD / 4);
        size_t off = (size_t)b * TT * DD + d4 * 4;
        *(float4*)(out + off) = *(const float4*)(x + off);
    } else if (i == nvec) {
        g_ortho = 0.0;
    } else if (i == nvec + 1) {
        g_ent = 0.0;
    }
}

__global__ void finalize_kernel(float* __restrict__ out) {
    if (threadIdx.x == 0) {
        out[NTOT]     = (float)(0.001 * g_ortho);
        out[NTOT + 1] = (float)(g_ent * (1.0 / (double)NTOK));
    }
}

// ---------------- x -> compact fp16 ----------------
__global__ void xconvert_kernel(const float* __restrict__ x) {
    int i = blockIdx.x * blockDim.x + threadIdx.x;
    if (i < NTOK * DD / 4) {
        int tok = i / (DD / 4);
        int d4 = (i % (DD / 4)) * 4;
        int b = tok >> 10;
        int t = (tok & 1023) + 1;
        float4 v = *(const float4*)(x + ((size_t)b * TT + t) * DD + d4);
        __half2 h0 = __floats2half2_rn(v.x, v.y);
        __half2 h1 = __floats2half2_rn(v.z, v.w);
        uint2 o = make_uint2(*(uint32_t*)&h0, *(uint32_t*)&h1);
        *(uint2*)(g_xth + (size_t)tok * DD + d4) = o;
    }
}

// ---------------- weights -> fp16 k-pair-interleaved ----------------
__global__ void wconvert_kernel(const float* __restrict__ Wd, const float* __restrict__ Wu,
                                const float* __restrict__ Q) {
    const int NW = (DD / 2) * N1;
    for (int i = blockIdx.x * blockDim.x + threadIdx.x; i < NW;
         i += gridDim.x * blockDim.x) {
        {
            int k2 = i / N1, n = i % N1;
            __half2 h = __floats2half2_rn(Wd[(size_t)n * DD + 2 * k2],
                                          Wd[(size_t)n * DD + 2 * k2 + 1]);
            g_wdt2[i] = *(uint32_t*)&h;
        }
        {
            int k2 = i / DD, d = i % DD;
            int k = 2 * k2;
            int e = k / CC, c = k % CC;
            __half2 h = __floats2half2_rn(Wu[((size_t)e * DD + d) * CC + c],
                                          Wu[((size_t)e * DD + d) * CC + c + 1]);
            g_wut2[i] = *(uint32_t*)&h;
        }
        if (i < (DD / 2) * RR) {
            int k2 = i / RR, r = i % RR;
            __half2 h = __floats2half2_rn(Q[(size_t)(2 * k2) * RR + r],
                                          Q[(size_t)(2 * k2 + 1) * RR + r]);
            g_qt2[i] = *(uint32_t*)&h;
        }
    }
}

// ---------------- ortho penalty (cooperative; exact splitK2 chains) -------
// 32 blocks: blocks 0..15 -> Q, 16..31 -> P; block handles 8 i-columns.
__global__ __launch_bounds__(256) void ortho_kernel(const float* __restrict__ Q,
                                                    const float* __restrict__ P) {
    __shared__ float col8[8][DD];       // 32 KB
    __shared__ double red[256];
    const float* M = (blockIdx.x < 16) ? Q : P;
    int i0 = (blockIdx.x & 15) * 8;
    int tid = threadIdx.x;
    for (int idx = tid; idx < 8 * DD; idx += 256) {
        int d = idx >> 3, ii = idx & 7;
        col8[ii][d] = M[(size_t)d * RR + i0 + ii];
    }
    __syncthreads();
    int j = tid & 127, ig = tid >> 7;   // ig in {0,1}: i = i0 + ig*4 + q
    float s1[4] = {0.f, 0.f, 0.f, 0.f};
    float s2[4] = {0.f, 0.f, 0.f, 0.f};
    #pragma unroll 4
    for (int d = 0; d < DD / 2; d++) {
        float mj = M[(size_t)d * RR + j];
        #pragma unroll
        for (int q = 0; q < 4; q++) s1[q] = fmaf(col8[ig * 4 + q][d], mj, s1[q]);
    }
    #pragma unroll 4
    for (int d = DD / 2; d < DD; d++) {
        float mj = M[(size_t)d * RR + j];
        #pragma unroll
        for (int q = 0; q < 4; q++) s2[q] = fmaf(col8[ig * 4 + q][d], mj, s2[q]);
    }
    double acc = 0.0;
    #pragma unroll
    for (int q = 0; q < 4; q++) {
        int i = i0 + ig * 4 + q;
        float G = s1[q] + s2[q];
        double r = (double)G - (i == j ? 1.0 : 0.0);
        acc += r * r;
    }
    red[tid] = acc;
    __syncthreads();
    for (int st = 128; st > 0; st >>= 1) {
        if (tid < st) red[tid] += red[tid + st];
        __syncthreads();
    }
    if (tid == 0) atomicAdd(&g_ortho, red[0]);
}

// ---------------- router (fp16 mma + fused softmax; R11 engine) ------------
__global__ __launch_bounds__(256) void router_kernel(
    const float* __restrict__ gamma, const float* __restrict__ masks,
    const float* __restrict__ bias) {
    extern __shared__ char smc[];
    __half* Ah = (__half*)smc;                            // [2][128][40]
    uint32_t* Bs2 = (uint32_t*)(smc + 2 * RA_BUF * 2);    // [2][16][136]
    float* zs = (float*)smc;                              // [128][129] alias
    float* gmv = (float*)(smc + 128 * RZS * 4);           // [8][129]
    __shared__ float entS[128];

    int tid = threadIdx.x;
    int lane = tid & 31, wid = tid >> 5;
    int wm = wid & 1, wn = wid >> 1;
    int g = lane >> 2, t = lane & 3;
    int tok0 = blockIdx.x * 128;
    const __half* arow = g_xth + (size_t)tok0 * DD;

    if (tid < 128) {
        float mv[EE];
        float mx = -1e30f;
        #pragma unroll
        for (int e = 0; e < EE; e++) { mv[e] = masks[e * RR + tid]; mx = fmaxf(mx, mv[e]); }
        float ss = 0.0f;
        #pragma unroll
        for (int e = 0; e < EE; e++) { mv[e] = expf(mv[e] - mx); ss += mv[e]; }
        float gsc = gamma[tid] / ss;
        #pragma unroll
        for (int e = 0; e < EE; e++) gmv[e * RZS + tid] = mv[e] * gsc;
    }

    float acc[16][4];
    #pragma unroll
    for (int i = 0; i < 16; i++)
        #pragma unroll
        for (int j = 0; j < 4; j++) acc[i][j] = 0.0f;

    #pragma unroll
    for (int l = 0; l < 2; l++) {
        int lin = tid + 256 * l;
        int row = lin >> 2, ch = (lin & 3) * 8;
        cp_async16(Ah + row * RA_STRIDE + ch, arow + (size_t)row * DD + ch);
        int kk = lin >> 5, c4 = (lin & 31) * 4;
        cp_async16(Bs2 + kk * 136 + c4, g_qt2 + (size_t)kk * RR + c4);
    }
    CP_COMMIT();

    const int NIT = DD / 32;
    for (int it = 0; it < NIT; it++) {
        int buf = it & 1;
        if (it + 1 < NIT) {
            int kb = (it + 1) * 32;
            int nbuf = buf ^ 1;
            #pragma unroll
            for (int l = 0; l < 2; l++) {
                int lin = tid + 256 * l;
                int row = lin >> 2, ch = (lin & 3) * 8;
                cp_async16(Ah + nbuf * RA_BUF + row * RA_STRIDE + ch,
                           arow + (size_t)row * DD + kb + ch);
                int kk = lin >> 5, c4 = (lin & 31) * 4;
                cp_async16(Bs2 + nbuf * RB_BUF + kk * 136 + c4,
                           g_qt2 + (size_t)(kb / 2 + kk) * RR + c4);
            }
            CP_COMMIT();
            CP_WAIT1();
        } else {
            CP_WAIT0();
        }
        __syncthreads();
        const __half* Ab = Ah + buf * RA_BUF;
        const uint32_t* Bb = Bs2 + buf * RB_BUF;
        #pragma unroll
        for (int ks = 0; ks < 2; ks++) {
            int k0 = ks * 16, k20 = ks * 8;
            uint32_t bfr[4][2];
            #pragma unroll
            for (int nf = 0; nf < 4; nf++) {
                int n0 = wn * 32 + nf * 8;
                bfr[nf][0] = Bb[(k20 + t) * 136 + n0 + g];
                bfr[nf][1] = Bb[(k20 + 4 + t) * 136 + n0 + g];
            }
            #pragma unroll
            for (int mf = 0; mf < 4; mf++) {
                int m0 = wm * 64 + mf * 16;
                uint32_t a0 = *(const uint32_t*)(Ab + (m0 + g) * RA_STRIDE + k0 + 2 * t);
                uint32_t a1 = *(const uint32_t*)(Ab + (m0 + g + 8) * RA_STRIDE + k0 + 2 * t);
                uint32_t a2 = *(const uint32_t*)(Ab + (m0 + g) * RA_STRIDE + k0 + 8 + 2 * t);
                uint32_t a3 = *(const uint32_t*)(Ab + (m0 + g + 8) * RA_STRIDE + k0 + 8 + 2 * t);
                #pragma unroll
                for (int nf = 0; nf < 4; nf++)
                    mma_f16(acc[mf * 4 + nf], a0, a1, a2, a3, bfr[nf][0], bfr[nf][1]);
            }
        }
        __syncthreads();
    }
    #pragma unroll
    for (int mf = 0; mf < 4; mf++) {
        #pragma unroll
        for (int nf = 0; nf < 4; nf++) {
            float* c = acc[mf * 4 + nf];
            int cl = wn * 32 + nf * 8 + 2 * t;
            #pragma unroll
            for (int h = 0; h < 2; h++) {
                int r = wm * 64 + mf * 16 + g + h * 8;
                zs[r * RZS + cl]     = c[h * 2] * c[h * 2];
                zs[r * RZS + cl + 1] = c[h * 2 + 1] * c[h * 2 + 1];
            }
        }
    }
    __syncthreads();

    if (tid < 128) {
        float s = 0.0f;
        float lg[EE];
        #pragma unroll
        for (int e = 0; e < EE; e++) lg[e] = 0.0f;
        #pragma unroll 4
        for (int r = 0; r < RR; r++) {
            float zq = zs[tid * RZS + r];
            s += zq;
            #pragma unroll
            for (int e = 0; e < EE; e++) lg[e] = fmaf(zq, gmv[e * RZS + r], lg[e]);
        }
        float sinv = 1.0f / (s + 1e-6f);
        float mx = -1e30f;
        #pragma unroll
        for (int e = 0; e < EE; e++) { lg[e] = lg[e] * sinv + bias[e]; mx = fmaxf(mx, lg[e]); }
        float ss = 0.0f;
        #pragma unroll
        for (int e = 0; e < EE; e++) { lg[e] = expf(lg[e] - mx); ss += lg[e]; }
        float inv = 1.0f / ss;
        float hent = 0.0f;
        #pragma unroll
        for (int e = 0; e < EE; e++) {
            float p = lg[e] * inv;
            hent -= p * logf(fmaxf(p, 1e-9f));
            g_probs[(size_t)(tok0 + tid) * EE + e] = p;
        }
        entS[tid] = hent;
    }
    __syncthreads();
    for (int st = 64; st > 0; st >>= 1) {
        if (tid < st && tid + st < 128) entS[tid] += entS[tid + st];
        __syncthreads();
    }
    if (tid == 0) atomicAdd(&g_ent, (double)entS[0]);
}

// ---------------- down GEMM (fp16 mma, BK=64 double-buffered) --------------
__global__ __launch_bounds__(256, 2) void down_kernel() {
    extern __shared__ char smc[];
    __half* Ah = (__half*)smc;                          // [2][128][72]
    uint32_t* Bs2 = (uint32_t*)(smc + 2 * ASH_BUF * 2); // [2][32][136]
    __shared__ float sh_probs[128][EE];
    int tid = threadIdx.x;
    int lane = tid & 31, wid = tid >> 5;
    int wm = wid & 1, wn = wid >> 1;
    int g = lane >> 2, t = lane & 3;
    int mb = blockIdx.y, nb = blockIdx.x;
    const __half* arow = g_xth + (size_t)mb * 128 * DD;

    {
        int r = tid >> 1, c4 = (tid & 1) * 4;
        *(float4*)&sh_probs[r][c4] =
            *(const float4*)(g_probs + (size_t)(mb * 128 + r) * EE + c4);
    }

    float acc[16][4];
    #pragma unroll
    for (int i = 0; i < 16; i++)
        #pragma unroll
        for (int j = 0; j < 4; j++) acc[i][j] = 0.0f;

    #pragma unroll
    for (int l = 0; l < 4; l++) {
        int lin = tid + 256 * l;
        int row = lin >> 3, ch = (lin & 7) * 8;
        cp_async16(Ah + row * ASH_STRIDE + ch, arow + (size_t)row * DD + ch);
        int kk = lin >> 5, c4 = (lin & 31) * 4;
        cp_async16(Bs2 + kk * BS2_STRIDE + c4,
                   g_wdt2 + (size_t)kk * N1 + nb * 128 + c4);
    }
    CP_COMMIT();

    const int NIT = DD / 64;
    for (int it = 0; it < NIT; it++) {
        int buf = it & 1;
        if (it + 1 < NIT) {
            int kb = (it + 1) * 64;
            int nbuf = buf ^ 1;
            #pragma unroll
            for (int l = 0; l < 4; l++) {
                int lin = tid + 256 * l;
                int row = lin >> 3, ch = (lin & 7) * 8;
                cp_async16(Ah + nbuf * ASH_BUF + row * ASH_STRIDE + ch,
                           arow + (size_t)row * DD + kb + ch);
                int kk = lin >> 5, c4 = (lin & 31) * 4;
                cp_async16(Bs2 + nbuf * BS2_BUF + kk * BS2_STRIDE + c4,
                           g_wdt2 + (size_t)(kb / 2 + kk) * N1 + nb * 128 + c4);
            }
            CP_COMMIT();
            CP_WAIT1();
        } else {
            CP_WAIT0();
        }
        __syncthreads();
        const __half* Ab = Ah + buf * ASH_BUF;
        const uint32_t* Bb = Bs2 + buf * BS2_BUF;
        #pragma unroll
        for (int ks = 0; ks < 4; ks++) {
            int k0 = ks * 16, k20 = ks * 8;
            uint32_t bfr[4][2];
            #pragma unroll
            for (int nf = 0; nf < 4; nf++) {
                int n0 = wn * 32 + nf * 8;
                bfr[nf][0] = Bb[(k20 + t) * BS2_STRIDE + n0 + g];
                bfr[nf][1] = Bb[(k20 + 4 + t) * BS2_STRIDE + n0 + g];
            }
            #pragma unroll
            for (int mf = 0; mf < 4; mf++) {
                int m0 = wm * 64 + mf * 16;
                uint32_t a0 = *(const uint32_t*)(Ab + (m0 + g) * ASH_STRIDE + k0 + 2 * t);
                uint32_t a1 = *(const uint32_t*)(Ab + (m0 + g + 8) * ASH_STRIDE + k0 + 2 * t);
                uint32_t a2 = *(const uint32_t*)(Ab + (m0 + g) * ASH_STRIDE + k0 + 8 + 2 * t);
                uint32_t a3 = *(const uint32_t*)(Ab + (m0 + g + 8) * ASH_STRIDE + k0 + 8 + 2 * t);
                #pragma unroll
                for (int nf = 0; nf < 4; nf++)
                    mma_f16(acc[mf * 4 + nf], a0, a1, a2, a3, bfr[nf][0], bfr[nf][1]);
            }
        }
        __syncthreads();
    }
    #pragma unroll
    for (int mf = 0; mf < 4; mf++) {
        #pragma unroll
        for (int nf = 0; nf < 4; nf++) {
            float* c = acc[mf * 4 + nf];
            int cl = wn * 32 + nf * 8 + 2 * t;
            int ncol = nb * 128 + cl;
            int e = ncol / CC;
            #pragma unroll
            for (int h = 0; h < 2; h++) {
                int r = wm * 64 + mf * 16 + g + h * 8;
                float p = sh_probs[r][e];
                float v0 = c[h * 2], v1 = c[h * 2 + 1];
                float g0 = 0.5f * v0 * (1.0f + erff(v0 * 0.70710678118654752f)) * p;
                float g1 = 0.5f * v1 * (1.0f + erff(v1 * 0.70710678118654752f)) * p;
                __half2 hv = __floats2half2_rn(g0, g1);
                *(uint32_t*)(g_midh + (size_t)(mb * 128 + r) * N1 + ncol) = *(uint32_t*)&hv;
            }
        }
    }
}

// ---------------- up GEMM (fp16 mma, BK=64 double-buffered) ----------------
__global__ __launch_bounds__(256, 2) void up_kernel(const float* __restrict__ x,
                                                    const float* __restrict__ alphap,
                                                    float* __restrict__ out) {
    extern __shared__ char smc[];
    __half* Ah = (__half*)smc;
    uint32_t* Bs2 = (uint32_t*)(smc + 2 * ASH_BUF * 2);
    int tid = threadIdx.x;
    int lane = tid & 31, wid = tid >> 5;
    int wm = wid & 1, wn = wid >> 1;
    int g = lane >> 2, t = lane & 3;
    int mb = blockIdx.y, nb = blockIdx.x;
    const __half* amid = g_midh + (size_t)mb * 128 * N1;

    float acc[16][4];
    #pragma unroll
    for (int i = 0; i < 16; i++)
        #pragma unroll
        for (int j = 0; j < 4; j++) acc[i][j] = 0.0f;

    #pragma unroll
    for (int l = 0; l < 4; l++) {
        int lin = tid + 256 * l;
        int row = lin >> 3, ch = (lin & 7) * 8;
        cp_async16(Ah + row * ASH_STRIDE + ch, amid + (size_t)row * N1 + ch);
        int kk = lin >> 5, c4 = (lin & 31) * 4;
        cp_async16(Bs2 + kk * BS2_STRIDE + c4,
                   g_wut2 + (size_t)kk * DD + nb * 128 + c4);
    }
    CP_COMMIT();

    const int NIT = N1 / 64;
    for (int it = 0; it < NIT; it++) {
        int buf = it & 1;
        if (it + 1 < NIT) {
            int kb = (it + 1) * 64;
            int nbuf = buf ^ 1;
            #pragma unroll
            for (int l = 0; l < 4; l++) {
                int lin = tid + 256 * l;
                int row = lin >> 3, ch = (lin & 7) * 8;
                cp_async16(Ah + nbuf * ASH_BUF + row * ASH_STRIDE + ch,
                           amid + (size_t)row * N1 + kb + ch);
                int kk = lin >> 5, c4 = (lin & 31) * 4;
                cp_async16(Bs2 + nbuf * BS2_BUF + kk * BS2_STRIDE + c4,
                           g_wut2 + (size_t)(kb / 2 + kk) * DD + nb * 128 + c4);
            }
            CP_COMMIT();
            CP_WAIT1();
        } else {
            CP_WAIT0();
        }
        __syncthreads();
        const __half* Ab = Ah + buf * ASH_BUF;
        const uint32_t* Bb = Bs2 + buf * BS2_BUF;
        #pragma unroll
        for (int ks = 0; ks < 4; ks++) {
            int k0 = ks * 16, k20 = ks * 8;
            uint32_t bfr[4][2];
            #pragma unroll
            for (int nf = 0; nf < 4; nf++) {
                int n0 = wn * 32 + nf * 8;
                bfr[nf][0] = Bb[(k20 + t) * BS2_STRIDE + n0 + g];
                bfr[nf][1] = Bb[(k20 + 4 + t) * BS2_STRIDE + n0 + g];
            }
            #pragma unroll
            for (int mf = 0; mf < 4; mf++) {
                int m0 = wm * 64 + mf * 16;
                uint32_t a0 = *(const uint32_t*)(Ab + (m0 + g) * ASH_STRIDE + k0 + 2 * t);
                uint32_t a1 = *(const uint32_t*)(Ab + (m0 + g + 8) * ASH_STRIDE + k0 + 2 * t);
                uint32_t a2 = *(const uint32_t*)(Ab + (m0 + g) * ASH_STRIDE + k0 + 8 + 2 * t);
                uint32_t a3 = *(const uint32_t*)(Ab + (m0 + g + 8) * ASH_STRIDE + k0 + 8 + 2 * t);
                #pragma unroll
                for (int nf = 0; nf < 4; nf++)
                    mma_f16(acc[mf * 4 + nf], a0, a1, a2, a3, bfr[nf][0], bfr[nf][1]);
            }
        }
        __syncthreads();
    }
    float alpha = *alphap;
    #pragma unroll
    for (int mf = 0; mf < 4; mf++) {
        #pragma unroll
        for (int nf = 0; nf < 4; nf++) {
            float* c = acc[mf * 4 + nf];
            int cl = wn * 32 + nf * 8 + 2 * t;
            int ncol = nb * 128 + cl;
            #pragma unroll
            for (int h = 0; h < 2; h++) {
                int r = wm * 64 + mf * 16 + g + h * 8;
                int gi = mb * 128 + r;
                int b = gi >> 10;
                int tt = (gi & 1023) + 1;
                size_t ro = ((size_t)b * TT + tt) * DD + ncol;
                float2 hx = *(const float2*)(x + ro);
                *(float2*)(out + ro) = make_float2(fmaf(alpha, c[h * 2], hx.x),
                                                   fmaf(alpha, c[h * 2 + 1], hx.y));
            }
        }
    }
}

// ---------------- launch ----------------
extern "C" void kernel_launch(void* const* d_in, const int* in_sizes, int n_in,
                              void* d_out, int out_size) {
    const float* x     = (const float*)d_in[0];
    const float* Q     = (const float*)d_in[1];
    const float* P     = (const float*)d_in[2];
    const float* gamma = (const float*)d_in[3];
    const float* masks = (const float*)d_in[4];
    const float* bias  = (const float*)d_in[5];
    const float* Wd    = (const float*)d_in[6];
    const float* Wu    = (const float*)d_in[7];
    const float* alpha = (const float*)d_in[8];
    float* out = (float*)d_out;

    cudaFuncSetAttribute(router_kernel,
                         cudaFuncAttributeMaxDynamicSharedMemorySize, ROUTER_DYN_SMEM);
    cudaFuncSetAttribute(down_kernel,
                         cudaFuncAttributeMaxDynamicSharedMemorySize, GEMM_DYN_SMEM);
    cudaFuncSetAttribute(up_kernel,
                         cudaFuncAttributeMaxDynamicSharedMemorySize, GEMM_DYN_SMEM);

    init_kernel<<<(BB * DD / 4 + 2 + 255) / 256, 256>>>(x, out);
    xconvert_kernel<<<(NTOK * DD / 4 + 255) / 256, 256>>>(x);
    wconvert_kernel<<<2048, 256>>>(Wd, Wu, Q);
    ortho_kernel<<<32, 256>>>(Q, P);
    router_kernel<<<NTOK / 128, 256, ROUTER_DYN_SMEM>>>(gamma, masks, bias);
    down_kernel<<<dim3(N1 / 128, NTOK / 128), 256, GEMM_DYN_SMEM>>>();
    up_kernel<<<dim3(DD / 128, NTOK / 128), 256, GEMM_DYN_SMEM>>>(x, alpha, out);
    finalize_kernel<<<1, 32>>>(out);
}

// round 15
// speedup vs baseline: 1.1003x; 1.1003x over previous
#include <cuda_runtime.h>
#include <cuda_fp16.h>
#include <math.h>
#include <stdint.h>

#define BB 16
#define TT 1025
#define DD 1024
#define EE 8
#define RR 128
#define CC 192
#define N1 1536            // EE*CC
#define NTOK 16384         // BB*(TT-1)
#define NTOT (16*1025*1024)

// -------- scratch (static device arrays; no allocations) --------
__device__ float g_probs[NTOK * EE];
__device__ __half g_xth[(size_t)NTOK * DD];                    // fp16 compact h
__device__ __half g_midh[(size_t)NTOK * N1];                   // fp16 mid
__device__ uint32_t g_wdt2[(size_t)(DD / 2) * N1];             // half2 [k/2][n]
__device__ uint32_t g_wut2[(size_t)(N1 / 2) * DD];             // half2 [k/2][d]
__device__ uint32_t g_qt2[(size_t)(DD / 2) * RR];              // half2 [k/2][r]
__device__ double g_ortho;
__device__ double g_ent;

// -------- helpers --------
__device__ __forceinline__ void mma_f16(float* c,
                                        uint32_t a0, uint32_t a1, uint32_t a2, uint32_t a3,
                                        uint32_t b0, uint32_t b1) {
    asm volatile("mma.sync.aligned.m16n8k16.row.col.f32.f16.f16.f32 "
                 "{%0,%1,%2,%3}, {%4,%5,%6,%7}, {%8,%9}, {%0,%1,%2,%3};"
                 : "+f"(c[0]), "+f"(c[1]), "+f"(c[2]), "+f"(c[3])
                 : "r"(a0), "r"(a1), "r"(a2), "r"(a3), "r"(b0), "r"(b1));
}
__device__ __forceinline__ void cp_async16(void* smem, const void* gmem) {
    uint32_t s = (uint32_t)__cvta_generic_to_shared(smem);
    asm volatile("cp.async.cg.shared.global [%0], [%1], 16;\n" :: "r"(s), "l"(gmem));
}
#define CP_COMMIT() asm volatile("cp.async.commit_group;\n" ::: "memory")
#define CP_WAIT1()  asm volatile("cp.async.wait_group 1;\n" ::: "memory")
#define CP_WAIT0()  asm volatile("cp.async.wait_group 0;\n" ::: "memory")

// GEMM SMEM geometry (BK=64): A [128][72] halves, B [32][136] half2
#define ASH_STRIDE 72
#define ASH_BUF (128 * ASH_STRIDE)          // 9216 halves / buffer
#define BS2_STRIDE 136
#define BS2_BUF (32 * BS2_STRIDE)           // 4352 u32 / buffer
#define GEMM_DYN_SMEM (2 * ASH_BUF * 2 + 2 * BS2_BUF * 4)      // 71680 B
// Router geometry (BK=32): A [128][40] halves, B [16][136] half2
#define RA_STRIDE 40
#define RA_BUF (128 * RA_STRIDE)
#define RB_BUF (16 * 136)
#define RZS 129
#define ROUTER_DYN_SMEM ((128 * RZS + EE * RZS) * 4)           // 70176 B

// ---------------- init ----------------
__global__ void init_kernel(const float* __restrict__ x, float* __restrict__ out) {
    int i = blockIdx.x * blockDim.x + threadIdx.x;
    int nvec = BB * DD / 4;
    if (i < nvec) {
        int b = i / (DD / 4);
        int d4 = i % (DD / 4);
        size_t off = (size_t)b * TT * DD + d4 * 4;
        *(float4*)(out + off) = *(const float4*)(x + off);
    } else if (i == nvec) {
        g_ortho = 0.0;
    } else if (i == nvec + 1) {
        g_ent = 0.0;
    }
}

__global__ void finalize_kernel(float* __restrict__ out) {
    if (threadIdx.x == 0) {
        out[NTOT]     = (float)(0.001 * g_ortho);
        out[NTOT + 1] = (float)(g_ent * (1.0 / (double)NTOK));
    }
}

// ---------------- x -> compact fp16 ----------------
__global__ void xconvert_kernel(const float* __restrict__ x) {
    int i = blockIdx.x * blockDim.x + threadIdx.x;
    if (i < NTOK * DD / 4) {
        int tok = i / (DD / 4);
        int d4 = (i % (DD / 4)) * 4;
        int b = tok >> 10;
        int t = (tok & 1023) + 1;
        float4 v = *(const float4*)(x + ((size_t)b * TT + t) * DD + d4);
        __half2 h0 = __floats2half2_rn(v.x, v.y);
        __half2 h1 = __floats2half2_rn(v.z, v.w);
        uint2 o = make_uint2(*(uint32_t*)&h0, *(uint32_t*)&h1);
        *(uint2*)(g_xth + (size_t)tok * DD + d4) = o;
    }
}

// ---------------- weights -> fp16 k-pair-interleaved ----------------
__global__ void wconvert_kernel(const float* __restrict__ Wd, const float* __restrict__ Wu,
                                const float* __restrict__ Q) {
    const int NW = (DD / 2) * N1;
    for (int i = blockIdx.x * blockDim.x + threadIdx.x; i < NW;
         i += gridDim.x * blockDim.x) {
        {
            int k2 = i / N1, n = i % N1;
            __half2 h = __floats2half2_rn(Wd[(size_t)n * DD + 2 * k2],
                                          Wd[(size_t)n * DD + 2 * k2 + 1]);
            g_wdt2[i] = *(uint32_t*)&h;
        }
        {
            int k2 = i / DD, d = i % DD;
            int k = 2 * k2;
            int e = k / CC, c = k % CC;
            __half2 h = __floats2half2_rn(Wu[((size_t)e * DD + d) * CC + c],
                                          Wu[((size_t)e * DD + d) * CC + c + 1]);
            g_wut2[i] = *(uint32_t*)&h;
        }
        if (i < (DD / 2) * RR) {
            int k2 = i / RR, r = i % RR;
            __half2 h = __floats2half2_rn(Q[(size_t)(2 * k2) * RR + r],
                                          Q[(size_t)(2 * k2 + 1) * RR + r]);
            g_qt2[i] = *(uint32_t*)&h;
        }
    }
}

// ---------------- ortho penalty (R5 proven: splitK=2 chains, fp64 sum) ----
// grid.x = 256: blocks 0..127 -> Q column i, 128..255 -> P column i
__global__ void ortho_kernel(const float* __restrict__ Q, const float* __restrict__ P) {
    const float* M = (blockIdx.x < RR) ? Q : P;
    int i = blockIdx.x & (RR - 1);
    __shared__ float col[DD];
    __shared__ double red[RR];
    for (int d = threadIdx.x; d < DD; d += RR) col[d] = M[(size_t)d * RR + i];
    __syncthreads();
    int j = threadIdx.x;
    float s1 = 0.0f, s2 = 0.0f;
    for (int d = 0; d < DD / 2; d++)
        s1 = fmaf(col[d], M[(size_t)d * RR + j], s1);
    for (int d = DD / 2; d < DD; d++)
        s2 = fmaf(col[d], M[(size_t)d * RR + j], s2);
    float G = s1 + s2;
    double r = (double)G - (j == i ? 1.0 : 0.0);
    red[j] = r * r;
    __syncthreads();
    for (int st = RR / 2; st > 0; st >>= 1) {
        if (j < st) red[j] += red[j + st];
        __syncthreads();
    }
    if (j == 0) atomicAdd(&g_ortho, red[0]);
}

// ---------------- router (fp16 mma + fused softmax; R11 engine) ------------
__global__ __launch_bounds__(256) void router_kernel(
    const float* __restrict__ gamma, const float* __restrict__ masks,
    const float* __restrict__ bias) {
    extern __shared__ char smc[];
    __half* Ah = (__half*)smc;                            // [2][128][40]
    uint32_t* Bs2 = (uint32_t*)(smc + 2 * RA_BUF * 2);    // [2][16][136]
    float* zs = (float*)smc;                              // [128][129] alias
    float* gmv = (float*)(smc + 128 * RZS * 4);           // [8][129]
    __shared__ float entS[128];

    int tid = threadIdx.x;
    int lane = tid & 31, wid = tid >> 5;
    int wm = wid & 1, wn = wid >> 1;
    int g = lane >> 2, t = lane & 3;
    int tok0 = blockIdx.x * 128;
    const __half* arow = g_xth + (size_t)tok0 * DD;

    if (tid < 128) {
        float mv[EE];
        float mx = -1e30f;
        #pragma unroll
        for (int e = 0; e < EE; e++) { mv[e] = masks[e * RR + tid]; mx = fmaxf(mx, mv[e]); }
        float ss = 0.0f;
        #pragma unroll
        for (int e = 0; e < EE; e++) { mv[e] = expf(mv[e] - mx); ss += mv[e]; }
        float gsc = gamma[tid] / ss;
        #pragma unroll
        for (int e = 0; e < EE; e++) gmv[e * RZS + tid] = mv[e] * gsc;
    }

    float acc[16][4];
    #pragma unroll
    for (int i = 0; i < 16; i++)
        #pragma unroll
        for (int j = 0; j < 4; j++) acc[i][j] = 0.0f;

    #pragma unroll
    for (int l = 0; l < 2; l++) {
        int lin = tid + 256 * l;
        int row = lin >> 2, ch = (lin & 3) * 8;
        cp_async16(Ah + row * RA_STRIDE + ch, arow + (size_t)row * DD + ch);
        int kk = lin >> 5, c4 = (lin & 31) * 4;
        cp_async16(Bs2 + kk * 136 + c4, g_qt2 + (size_t)kk * RR + c4);
    }
    CP_COMMIT();

    const int NIT = DD / 32;
    for (int it = 0; it < NIT; it++) {
        int buf = it & 1;
        if (it + 1 < NIT) {
            int kb = (it + 1) * 32;
            int nbuf = buf ^ 1;
            #pragma unroll
            for (int l = 0; l < 2; l++) {
                int lin = tid + 256 * l;
                int row = lin >> 2, ch = (lin & 3) * 8;
                cp_async16(Ah + nbuf * RA_BUF + row * RA_STRIDE + ch,
                           arow + (size_t)row * DD + kb + ch);
                int kk = lin >> 5, c4 = (lin & 31) * 4;
                cp_async16(Bs2 + nbuf * RB_BUF + kk * 136 + c4,
                           g_qt2 + (size_t)(kb / 2 + kk) * RR + c4);
            }
            CP_COMMIT();
            CP_WAIT1();
        } else {
            CP_WAIT0();
        }
        __syncthreads();
        const __half* Ab = Ah + buf * RA_BUF;
        const uint32_t* Bb = Bs2 + buf * RB_BUF;
        #pragma unroll
        for (int ks = 0; ks < 2; ks++) {
            int k0 = ks * 16, k20 = ks * 8;
            uint32_t bfr[4][2];
            #pragma unroll
            for (int nf = 0; nf < 4; nf++) {
                int n0 = wn * 32 + nf * 8;
                bfr[nf][0] = Bb[(k20 + t) * 136 + n0 + g];
                bfr[nf][1] = Bb[(k20 + 4 + t) * 136 + n0 + g];
            }
            #pragma unroll
            for (int mf = 0; mf < 4; mf++) {
                int m0 = wm * 64 + mf * 16;
                uint32_t a0 = *(const uint32_t*)(Ab + (m0 + g) * RA_STRIDE + k0 + 2 * t);
                uint32_t a1 = *(const uint32_t*)(Ab + (m0 + g + 8) * RA_STRIDE + k0 + 2 * t);
                uint32_t a2 = *(const uint32_t*)(Ab + (m0 + g) * RA_STRIDE + k0 + 8 + 2 * t);
                uint32_t a3 = *(const uint32_t*)(Ab + (m0 + g + 8) * RA_STRIDE + k0 + 8 + 2 * t);
                #pragma unroll
                for (int nf = 0; nf < 4; nf++)
                    mma_f16(acc[mf * 4 + nf], a0, a1, a2, a3, bfr[nf][0], bfr[nf][1]);
            }
        }
        __syncthreads();
    }
    #pragma unroll
    for (int mf = 0; mf < 4; mf++) {
        #pragma unroll
        for (int nf = 0; nf < 4; nf++) {
            float* c = acc[mf * 4 + nf];
            int cl = wn * 32 + nf * 8 + 2 * t;
            #pragma unroll
            for (int h = 0; h < 2; h++) {
                int r = wm * 64 + mf * 16 + g + h * 8;
                zs[r * RZS + cl]     = c[h * 2] * c[h * 2];
                zs[r * RZS + cl + 1] = c[h * 2 + 1] * c[h * 2 + 1];
            }
        }
    }
    __syncthreads();

    if (tid < 128) {
        float s = 0.0f;
        float lg[EE];
        #pragma unroll
        for (int e = 0; e < EE; e++) lg[e] = 0.0f;
        #pragma unroll 4
        for (int r = 0; r < RR; r++) {
            float zq = zs[tid * RZS + r];
            s += zq;
            #pragma unroll
            for (int e = 0; e < EE; e++) lg[e] = fmaf(zq, gmv[e * RZS + r], lg[e]);
        }
        float sinv = 1.0f / (s + 1e-6f);
        float mx = -1e30f;
        #pragma unroll
        for (int e = 0; e < EE; e++) { lg[e] = lg[e] * sinv + bias[e]; mx = fmaxf(mx, lg[e]); }
        float ss = 0.0f;
        #pragma unroll
        for (int e = 0; e < EE; e++) { lg[e] = expf(lg[e] - mx); ss += lg[e]; }
        float inv = 1.0f / ss;
        float hent = 0.0f;
        #pragma unroll
        for (int e = 0; e < EE; e++) {
            float p = lg[e] * inv;
            hent -= p * logf(fmaxf(p, 1e-9f));
            g_probs[(size_t)(tok0 + tid) * EE + e] = p;
        }
        entS[tid] = hent;
    }
    __syncthreads();
    for (int st = 64; st > 0; st >>= 1) {
        if (tid < st && tid + st < 128) entS[tid] += entS[tid + st];
        __syncthreads();
    }
    if (tid == 0) atomicAdd(&g_ent, (double)entS[0]);
}

// ---------------- down GEMM (fp16 mma, BK=64 double-buffered) --------------
__global__ __launch_bounds__(256, 2) void down_kernel() {
    extern __shared__ char smc[];
    __half* Ah = (__half*)smc;                          // [2][128][72]
    uint32_t* Bs2 = (uint32_t*)(smc + 2 * ASH_BUF * 2); // [2][32][136]
    __shared__ float sh_probs[128][EE];
    int tid = threadIdx.x;
    int lane = tid & 31, wid = tid >> 5;
    int wm = wid & 1, wn = wid >> 1;
    int g = lane >> 2, t = lane & 3;
    int mb = blockIdx.y, nb = blockIdx.x;
    const __half* arow = g_xth + (size_t)mb * 128 * DD;

    {
        int r = tid >> 1, c4 = (tid & 1) * 4;
        *(float4*)&sh_probs[r][c4] =
            *(const float4*)(g_probs + (size_t)(mb * 128 + r) * EE + c4);
    }

    float acc[16][4];
    #pragma unroll
    for (int i = 0; i < 16; i++)
        #pragma unroll
        for (int j = 0; j < 4; j++) acc[i][j] = 0.0f;

    #pragma unroll
    for (int l = 0; l < 4; l++) {
        int lin = tid + 256 * l;
        int row = lin >> 3, ch = (lin & 7) * 8;
        cp_async16(Ah + row * ASH_STRIDE + ch, arow + (size_t)row * DD + ch);
        int kk = lin >> 5, c4 = (lin & 31) * 4;
        cp_async16(Bs2 + kk * BS2_STRIDE + c4,
                   g_wdt2 + (size_t)kk * N1 + nb * 128 + c4);
    }
    CP_COMMIT();

    const int NIT = DD / 64;
    for (int it = 0; it < NIT; it++) {
        int buf = it & 1;
        if (it + 1 < NIT) {
            int kb = (it + 1) * 64;
            int nbuf = buf ^ 1;
            #pragma unroll
            for (int l = 0; l < 4; l++) {
                int lin = tid + 256 * l;
                int row = lin >> 3, ch = (lin & 7) * 8;
                cp_async16(Ah + nbuf * ASH_BUF + row * ASH_STRIDE + ch,
                           arow + (size_t)row * DD + kb + ch);
                int kk = lin >> 5, c4 = (lin & 31) * 4;
                cp_async16(Bs2 + nbuf * BS2_BUF + kk * BS2_STRIDE + c4,
                           g_wdt2 + (size_t)(kb / 2 + kk) * N1 + nb * 128 + c4);
            }
            CP_COMMIT();
            CP_WAIT1();
        } else {
            CP_WAIT0();
        }
        __syncthreads();
        const __half* Ab = Ah + buf * ASH_BUF;
        const uint32_t* Bb = Bs2 + buf * BS2_BUF;
        #pragma unroll
        for (int ks = 0; ks < 4; ks++) {
            int k0 = ks * 16, k20 = ks * 8;
            uint32_t bfr[4][2];
            #pragma unroll
            for (int nf = 0; nf < 4; nf++) {
                int n0 = wn * 32 + nf * 8;
                bfr[nf][0] = Bb[(k20 + t) * BS2_STRIDE + n0 + g];
                bfr[nf][1] = Bb[(k20 + 4 + t) * BS2_STRIDE + n0 + g];
            }
            #pragma unroll
            for (int mf = 0; mf < 4; mf++) {
                int m0 = wm * 64 + mf * 16;
                uint32_t a0 = *(const uint32_t*)(Ab + (m0 + g) * ASH_STRIDE + k0 + 2 * t);
                uint32_t a1 = *(const uint32_t*)(Ab + (m0 + g + 8) * ASH_STRIDE + k0 + 2 * t);
                uint32_t a2 = *(const uint32_t*)(Ab + (m0 + g) * ASH_STRIDE + k0 + 8 + 2 * t);
                uint32_t a3 = *(const uint32_t*)(Ab + (m0 + g + 8) * ASH_STRIDE + k0 + 8 + 2 * t);
                #pragma unroll
                for (int nf = 0; nf < 4; nf++)
                    mma_f16(acc[mf * 4 + nf], a0, a1, a2, a3, bfr[nf][0], bfr[nf][1]);
            }
        }
        __syncthreads();
    }
    #pragma unroll
    for (int mf = 0; mf < 4; mf++) {
        #pragma unroll
        for (int nf = 0; nf < 4; nf++) {
            float* c = acc[mf * 4 + nf];
            int cl = wn * 32 + nf * 8 + 2 * t;
            int ncol = nb * 128 + cl;
            int e = ncol / CC;
            #pragma unroll
            for (int h = 0; h < 2; h++) {
                int r = wm * 64 + mf * 16 + g + h * 8;
                float p = sh_probs[r][e];
                float v0 = c[h * 2], v1 = c[h * 2 + 1];
                float g0 = 0.5f * v0 * (1.0f + erff(v0 * 0.70710678118654752f)) * p;
                float g1 = 0.5f * v1 * (1.0f + erff(v1 * 0.70710678118654752f)) * p;
                __half2 hv = __floats2half2_rn(g0, g1);
                *(uint32_t*)(g_midh + (size_t)(mb * 128 + r) * N1 + ncol) = *(uint32_t*)&hv;
            }
        }
    }
}

// ---------------- up GEMM (fp16 mma, BK=64 double-buffered) ----------------
__global__ __launch_bounds__(256, 2) void up_kernel(const float* __restrict__ x,
                                                    const float* __restrict__ alphap,
                                                    float* __restrict__ out) {
    extern __shared__ char smc[];
    __half* Ah = (__half*)smc;
    uint32_t* Bs2 = (uint32_t*)(smc + 2 * ASH_BUF * 2);
    int tid = threadIdx.x;
    int lane = tid & 31, wid = tid >> 5;
    int wm = wid & 1, wn = wid >> 1;
    int g = lane >> 2, t = lane & 3;
    int mb = blockIdx.y, nb = blockIdx.x;
    const __half* amid = g_midh + (size_t)mb * 128 * N1;

    float acc[16][4];
    #pragma unroll
    for (int i = 0; i < 16; i++)
        #pragma unroll
        for (int j = 0; j < 4; j++) acc[i][j] = 0.0f;

    #pragma unroll
    for (int l = 0; l < 4; l++) {
        int lin = tid + 256 * l;
        int row = lin >> 3, ch = (lin & 7) * 8;
        cp_async16(Ah + row * ASH_STRIDE + ch, amid + (size_t)row * N1 + ch);
        int kk = lin >> 5, c4 = (lin & 31) * 4;
        cp_async16(Bs2 + kk * BS2_STRIDE + c4,
                   g_wut2 + (size_t)kk * DD + nb * 128 + c4);
    }
    CP_COMMIT();

    const int NIT = N1 / 64;
    for (int it = 0; it < NIT; it++) {
        int buf = it & 1;
        if (it + 1 < NIT) {
            int kb = (it + 1) * 64;
            int nbuf = buf ^ 1;
            #pragma unroll
            for (int l = 0; l < 4; l++) {
                int lin = tid + 256 * l;
                int row = lin >> 3, ch = (lin & 7) * 8;
                cp_async16(Ah + nbuf * ASH_BUF + row * ASH_STRIDE + ch,
                           amid + (size_t)row * N1 + kb + ch);
                int kk = lin >> 5, c4 = (lin & 31) * 4;
                cp_async16(Bs2 + nbuf * BS2_BUF + kk * BS2_STRIDE + c4,
                           g_wut2 + (size_t)(kb / 2 + kk) * DD + nb * 128 + c4);
            }
            CP_COMMIT();
            CP_WAIT1();
        } else {
            CP_WAIT0();
        }
        __syncthreads();
        const __half* Ab = Ah + buf * ASH_BUF;
        const uint32_t* Bb = Bs2 + buf * BS2_BUF;
        #pragma unroll
        for (int ks = 0; ks < 4; ks++) {
            int k0 = ks * 16, k20 = ks * 8;
            uint32_t bfr[4][2];
            #pragma unroll
            for (int nf = 0; nf < 4; nf++) {
                int n0 = wn * 32 + nf * 8;
                bfr[nf][0] = Bb[(k20 + t) * BS2_STRIDE + n0 + g];
                bfr[nf][1] = Bb[(k20 + 4 + t) * BS2_STRIDE + n0 + g];
            }
            #pragma unroll
            for (int mf = 0; mf < 4; mf++) {
                int m0 = wm * 64 + mf * 16;
                uint32_t a0 = *(const uint32_t*)(Ab + (m0 + g) * ASH_STRIDE + k0 + 2 * t);
                uint32_t a1 = *(const uint32_t*)(Ab + (m0 + g + 8) * ASH_STRIDE + k0 + 2 * t);
                uint32_t a2 = *(const uint32_t*)(Ab + (m0 + g) * ASH_STRIDE + k0 + 8 + 2 * t);
                uint32_t a3 = *(const uint32_t*)(Ab + (m0 + g + 8) * ASH_STRIDE + k0 + 8 + 2 * t);
                #pragma unroll
                for (int nf = 0; nf < 4; nf++)
                    mma_f16(acc[mf * 4 + nf], a0, a1, a2, a3, bfr[nf][0], bfr[nf][1]);
            }
        }
        __syncthreads();
    }
    float alpha = *alphap;
    #pragma unroll
    for (int mf = 0; mf < 4; mf++) {
        #pragma unroll
        for (int nf = 0; nf < 4; nf++) {
            float* c = acc[mf * 4 + nf];
            int cl = wn * 32 + nf * 8 + 2 * t;
            int ncol = nb * 128 + cl;
            #pragma unroll
            for (int h = 0; h < 2; h++) {
                int r = wm * 64 + mf * 16 + g + h * 8;
                int gi = mb * 128 + r;
                int b = gi >> 10;
                int tt = (gi & 1023) + 1;
                size_t ro = ((size_t)b * TT + tt) * DD + ncol;
                float2 hx = *(const float2*)(x + ro);
                *(float2*)(out + ro) = make_float2(fmaf(alpha, c[h * 2], hx.x),
                                                   fmaf(alpha, c[h * 2 + 1], hx.y));
            }
        }
    }
}

// ---------------- launch ----------------
extern "C" void kernel_launch(void* const* d_in, const int* in_sizes, int n_in,
                              void* d_out, int out_size) {
    const float* x     = (const float*)d_in[0];
    const float* Q     = (const float*)d_in[1];
    const float* P     = (const float*)d_in[2];
    const float* gamma = (const float*)d_in[3];
    const float* masks = (const float*)d_in[4];
    const float* bias  = (const float*)d_in[5];
    const float* Wd    = (const float*)d_in[6];
    const float* Wu    = (const float*)d_in[7];
    const float* alpha = (const float*)d_in[8];
    float* out = (float*)d_out;

    cudaFuncSetAttribute(router_kernel,
                         cudaFuncAttributeMaxDynamicSharedMemorySize, ROUTER_DYN_SMEM);
    cudaFuncSetAttribute(down_kernel,
                         cudaFuncAttributeMaxDynamicSharedMemorySize, GEMM_DYN_SMEM);
    cudaFuncSetAttribute(up_kernel,
                         cudaFuncAttributeMaxDynamicSharedMemorySize, GEMM_DYN_SMEM);

    init_kernel<<<(BB * DD / 4 + 2 + 255) / 256, 256>>>(x, out);
    xconvert_kernel<<<(NTOK * DD / 4 + 255) / 256, 256>>>(x);
    wconvert_kernel<<<2048, 256>>>(Wd, Wu, Q);
    ortho_kernel<<<2 * RR, RR>>>(Q, P);
    router_kernel<<<NTOK / 128, 256, ROUTER_DYN_SMEM>>>(gamma, masks, bias);
    down_kernel<<<dim3(N1 / 128, NTOK / 128), 256, GEMM_DYN_SMEM>>>();
    up_kernel<<<dim3(DD / 128, NTOK / 128), 256, GEMM_DYN_SMEM>>>(x, alpha, out);
    finalize_kernel<<<1, 32>>>(out);
}

// round 16
// speedup vs baseline: 1.1887x; 1.0803x over previous
#include <cuda_runtime.h>
#include <cuda_fp16.h>
#include <math.h>
#include <stdint.h>

#define BB 16
#define TT 1025
#define DD 1024
#define EE 8
#define RR 128
#define CC 192
#define N1 1536            // EE*CC
#define NTOK 16384         // BB*(TT-1)
#define NTOT (16*1025*1024)

// -------- scratch (static device arrays; no allocations) --------
__device__ float g_probs[NTOK * EE];
__device__ __half g_xth[(size_t)NTOK * DD];                    // fp16 compact h
__device__ __half g_midh[(size_t)NTOK * N1];                   // fp16 mid
__device__ uint32_t g_wdt2[(size_t)(DD / 2) * N1];             // half2 [k/2][n]
__device__ uint32_t g_wut2[(size_t)(N1 / 2) * DD];             // half2 [k/2][d]
__device__ uint32_t g_qt2[(size_t)(DD / 2) * RR];              // half2 [k/2][r]
__device__ double g_ortho;
__device__ double g_ent;

// -------- helpers --------
__device__ __forceinline__ void mma_f16(float* c,
                                        uint32_t a0, uint32_t a1, uint32_t a2, uint32_t a3,
                                        uint32_t b0, uint32_t b1) {
    asm volatile("mma.sync.aligned.m16n8k16.row.col.f32.f16.f16.f32 "
                 "{%0,%1,%2,%3}, {%4,%5,%6,%7}, {%8,%9}, {%0,%1,%2,%3};"
                 : "+f"(c[0]), "+f"(c[1]), "+f"(c[2]), "+f"(c[3])
                 : "r"(a0), "r"(a1), "r"(a2), "r"(a3), "r"(b0), "r"(b1));
}
__device__ __forceinline__ void cp_async16(void* smem, const void* gmem) {
    uint32_t s = (uint32_t)__cvta_generic_to_shared(smem);
    asm volatile("cp.async.cg.shared.global [%0], [%1], 16;\n" :: "r"(s), "l"(gmem));
}
#define CP_COMMIT() asm volatile("cp.async.commit_group;\n" ::: "memory")
#define CP_WAIT1()  asm volatile("cp.async.wait_group 1;\n" ::: "memory")
#define CP_WAIT0()  asm volatile("cp.async.wait_group 0;\n" ::: "memory")

// GEMM SMEM geometry (BK=64): A [128][72] halves, B [32][136] half2
#define ASH_STRIDE 72
#define ASH_BUF (128 * ASH_STRIDE)
#define BS2_STRIDE 136
#define BS2_BUF (32 * BS2_STRIDE)
#define GEMM_DYN_SMEM (2 * ASH_BUF * 2 + 2 * BS2_BUF * 4)      // 71680 B
// Router geometry (BK=32): A [128][40] halves, B [16][136] half2
#define RA_STRIDE 40
#define RA_BUF (128 * RA_STRIDE)
#define RB_BUF (16 * 136)
#define RZS 129
#define ROUTER_DYN_SMEM ((128 * RZS + EE * RZS) * 4)           // 70176 B

// ---------------- finalize ----------------
__global__ void finalize_kernel(float* __restrict__ out) {
    if (threadIdx.x == 0) {
        out[NTOT]     = (float)(0.001 * g_ortho);
        out[NTOT + 1] = (float)(g_ent * (1.0 / (double)NTOK));
    }
}

// ---------------- prep: init + xconvert + wconvert in one launch ----------
__global__ __launch_bounds__(256) void prep_kernel(
    const float* __restrict__ x, const float* __restrict__ Wd,
    const float* __restrict__ Wu, const float* __restrict__ Q,
    float* __restrict__ out) {
    int gtid = blockIdx.x * blockDim.x + threadIdx.x;
    int stride = gridDim.x * blockDim.x;
    if (gtid == 0) { g_ortho = 0.0; g_ent = 0.0; }
    // CLS copy
    for (int i = gtid; i < BB * DD / 4; i += stride) {
        int b = i / (DD / 4);
        int d4 = i % (DD / 4);
        size_t off = (size_t)b * TT * DD + d4 * 4;
        *(float4*)(out + off) = *(const float4*)(x + off);
    }
    // x -> compact fp16
    for (int i = gtid; i < NTOK * DD / 4; i += stride) {
        int tok = i / (DD / 4);
        int d4 = (i % (DD / 4)) * 4;
        int b = tok >> 10;
        int t = (tok & 1023) + 1;
        float4 v = *(const float4*)(x + ((size_t)b * TT + t) * DD + d4);
        __half2 h0 = __floats2half2_rn(v.x, v.y);
        __half2 h1 = __floats2half2_rn(v.z, v.w);
        uint2 o = make_uint2(*(uint32_t*)&h0, *(uint32_t*)&h1);
        *(uint2*)(g_xth + (size_t)tok * DD + d4) = o;
    }
    // weights -> fp16 k-pair-interleaved
    for (int i = gtid; i < (DD / 2) * N1; i += stride) {
        {
            int k2 = i / N1, n = i % N1;
            __half2 h = __floats2half2_rn(Wd[(size_t)n * DD + 2 * k2],
                                          Wd[(size_t)n * DD + 2 * k2 + 1]);
            g_wdt2[i] = *(uint32_t*)&h;
        }
        {
            int k2 = i / DD, d = i % DD;
            int k = 2 * k2;
            int e = k / CC, c = k % CC;
            __half2 h = __floats2half2_rn(Wu[((size_t)e * DD + d) * CC + c],
                                          Wu[((size_t)e * DD + d) * CC + c + 1]);
            g_wut2[i] = *(uint32_t*)&h;
        }
        if (i < (DD / 2) * RR) {
            int k2 = i / RR, r = i % RR;
            __half2 h = __floats2half2_rn(Q[(size_t)(2 * k2) * RR + r],
                                          Q[(size_t)(2 * k2 + 1) * RR + r]);
            g_qt2[i] = *(uint32_t*)&h;
        }
    }
}

// ---------------- router + ortho fused launch ----------------
// Blocks 0..127: router for 128 tokens each (R11 engine, unchanged math).
// Blocks 128..255: ortho, 2 Gram columns per block (R5 splitK2 chains,
// per-entry bit-identical). Backfills SMs left idle by the router wave.
__global__ __launch_bounds__(256) void router_kernel(
    const float* __restrict__ gamma, const float* __restrict__ masks,
    const float* __restrict__ bias,
    const float* __restrict__ Qf, const float* __restrict__ Pf) {
    extern __shared__ char smc[];
    __shared__ float entS[128];
    __shared__ float col2[2][DD];
    __shared__ double red2[2][128];

    int tid = threadIdx.x;

    if (blockIdx.x >= 128) {
        // ---------------- ortho path ----------------
        int ob = blockIdx.x - 128;          // 0..127
        const float* M = (ob < 64) ? Qf : Pf;
        int i0 = (ob & 63) * 2;
        for (int idx = tid; idx < 2 * DD; idx += 256) {
            int cc = idx >> 10, d = idx & 1023;
            col2[cc][d] = M[(size_t)d * RR + i0 + cc];
        }
        __syncthreads();
        int hf = tid >> 7;                  // column i0+hf
        int j = tid & 127;
        float s1 = 0.0f, s2 = 0.0f;
        for (int d = 0; d < DD / 2; d++)
            s1 = fmaf(col2[hf][d], M[(size_t)d * RR + j], s1);
        for (int d = DD / 2; d < DD; d++)
            s2 = fmaf(col2[hf][d], M[(size_t)d * RR + j], s2);
        float G = s1 + s2;
        double r = (double)G - (j == i0 + hf ? 1.0 : 0.0);
        red2[hf][j] = r * r;
        __syncthreads();
        for (int st = 64; st > 0; st >>= 1) {
            if (j < st) red2[hf][j] += red2[hf][j + st];
            __syncthreads();
        }
        if (j == 0) atomicAdd(&g_ortho, red2[hf][0]);
        return;
    }

    // ---------------- router path ----------------
    __half* Ah = (__half*)smc;                            // [2][128][40]
    uint32_t* Bs2 = (uint32_t*)(smc + 2 * RA_BUF * 2);    // [2][16][136]
    float* zs = (float*)smc;                              // [128][129] alias
    float* gmv = (float*)(smc + 128 * RZS * 4);           // [8][129]

    int lane = tid & 31, wid = tid >> 5;
    int wm = wid & 1, wn = wid >> 1;
    int g = lane >> 2, t = lane & 3;
    int tok0 = blockIdx.x * 128;
    const __half* arow = g_xth + (size_t)tok0 * DD;

    if (tid < 128) {
        float mv[EE];
        float mx = -1e30f;
        #pragma unroll
        for (int e = 0; e < EE; e++) { mv[e] = masks[e * RR + tid]; mx = fmaxf(mx, mv[e]); }
        float ss = 0.0f;
        #pragma unroll
        for (int e = 0; e < EE; e++) { mv[e] = expf(mv[e] - mx); ss += mv[e]; }
        float gsc = gamma[tid] / ss;
        #pragma unroll
        for (int e = 0; e < EE; e++) gmv[e * RZS + tid] = mv[e] * gsc;
    }

    float acc[16][4];
    #pragma unroll
    for (int i = 0; i < 16; i++)
        #pragma unroll
        for (int j = 0; j < 4; j++) acc[i][j] = 0.0f;

    #pragma unroll
    for (int l = 0; l < 2; l++) {
        int lin = tid + 256 * l;
        int row = lin >> 2, ch = (lin & 3) * 8;
        cp_async16(Ah + row * RA_STRIDE + ch, arow + (size_t)row * DD + ch);
        int kk = lin >> 5, c4 = (lin & 31) * 4;
        cp_async16(Bs2 + kk * 136 + c4, g_qt2 + (size_t)kk * RR + c4);
    }
    CP_COMMIT();

    const int NIT = DD / 32;
    for (int it = 0; it < NIT; it++) {
        int buf = it & 1;
        if (it + 1 < NIT) {
            int kb = (it + 1) * 32;
            int nbuf = buf ^ 1;
            #pragma unroll
            for (int l = 0; l < 2; l++) {
                int lin = tid + 256 * l;
                int row = lin >> 2, ch = (lin & 3) * 8;
                cp_async16(Ah + nbuf * RA_BUF + row * RA_STRIDE + ch,
                           arow + (size_t)row * DD + kb + ch);
                int kk = lin >> 5, c4 = (lin & 31) * 4;
                cp_async16(Bs2 + nbuf * RB_BUF + kk * 136 + c4,
                           g_qt2 + (size_t)(kb / 2 + kk) * RR + c4);
            }
            CP_COMMIT();
            CP_WAIT1();
        } else {
            CP_WAIT0();
        }
        __syncthreads();
        const __half* Ab = Ah + buf * RA_BUF;
        const uint32_t* Bb = Bs2 + buf * RB_BUF;
        #pragma unroll
        for (int ks = 0; ks < 2; ks++) {
            int k0 = ks * 16, k20 = ks * 8;
            uint32_t bfr[4][2];
            #pragma unroll
            for (int nf = 0; nf < 4; nf++) {
                int n0 = wn * 32 + nf * 8;
                bfr[nf][0] = Bb[(k20 + t) * 136 + n0 + g];
                bfr[nf][1] = Bb[(k20 + 4 + t) * 136 + n0 + g];
            }
            #pragma unroll
            for (int mf = 0; mf < 4; mf++) {
                int m0 = wm * 64 + mf * 16;
                uint32_t a0 = *(const uint32_t*)(Ab + (m0 + g) * RA_STRIDE + k0 + 2 * t);
                uint32_t a1 = *(const uint32_t*)(Ab + (m0 + g + 8) * RA_STRIDE + k0 + 2 * t);
                uint32_t a2 = *(const uint32_t*)(Ab + (m0 + g) * RA_STRIDE + k0 + 8 + 2 * t);
                uint32_t a3 = *(const uint32_t*)(Ab + (m0 + g + 8) * RA_STRIDE + k0 + 8 + 2 * t);
                #pragma unroll
                for (int nf = 0; nf < 4; nf++)
                    mma_f16(acc[mf * 4 + nf], a0, a1, a2, a3, bfr[nf][0], bfr[nf][1]);
            }
        }
        __syncthreads();
    }
    #pragma unroll
    for (int mf = 0; mf < 4; mf++) {
        #pragma unroll
        for (int nf = 0; nf < 4; nf++) {
            float* c = acc[mf * 4 + nf];
            int cl = wn * 32 + nf * 8 + 2 * t;
            #pragma unroll
            for (int h = 0; h < 2; h++) {
                int r = wm * 64 + mf * 16 + g + h * 8;
                zs[r * RZS + cl]     = c[h * 2] * c[h * 2];
                zs[r * RZS + cl + 1] = c[h * 2 + 1] * c[h * 2 + 1];
            }
        }
    }
    __syncthreads();

    if (tid < 128) {
        float s = 0.0f;
        float lg[EE];
        #pragma unroll
        for (int e = 0; e < EE; e++) lg[e] = 0.0f;
        #pragma unroll 4
        for (int r = 0; r < RR; r++) {
            float zq = zs[tid * RZS + r];
            s += zq;
            #pragma unroll
            for (int e = 0; e < EE; e++) lg[e] = fmaf(zq, gmv[e * RZS + r], lg[e]);
        }
        float sinv = 1.0f / (s + 1e-6f);
        float mx = -1e30f;
        #pragma unroll
        for (int e = 0; e < EE; e++) { lg[e] = lg[e] * sinv + bias[e]; mx = fmaxf(mx, lg[e]); }
        float ss = 0.0f;
        #pragma unroll
        for (int e = 0; e < EE; e++) { lg[e] = expf(lg[e] - mx); ss += lg[e]; }
        float inv = 1.0f / ss;
        float hent = 0.0f;
        #pragma unroll
        for (int e = 0; e < EE; e++) {
            float p = lg[e] * inv;
            hent -= p * logf(fmaxf(p, 1e-9f));
            g_probs[(size_t)(tok0 + tid) * EE + e] = p;
        }
        entS[tid] = hent;
    }
    __syncthreads();
    for (int st = 64; st > 0; st >>= 1) {
        if (tid < st && tid + st < 128) entS[tid] += entS[tid + st];
        __syncthreads();
    }
    if (tid == 0) atomicAdd(&g_ent, (double)entS[0]);
}

// ---------------- down GEMM (fp16 mma, BK=64 double-buffered) --------------
__global__ __launch_bounds__(256, 2) void down_kernel() {
    extern __shared__ char smc[];
    __half* Ah = (__half*)smc;                          // [2][128][72]
    uint32_t* Bs2 = (uint32_t*)(smc + 2 * ASH_BUF * 2); // [2][32][136]
    __shared__ float sh_probs[128][EE];
    int tid = threadIdx.x;
    int lane = tid & 31, wid = tid >> 5;
    int wm = wid & 1, wn = wid >> 1;
    int g = lane >> 2, t = lane & 3;
    int mb = blockIdx.y, nb = blockIdx.x;
    const __half* arow = g_xth + (size_t)mb * 128 * DD;

    {
        int r = tid >> 1, c4 = (tid & 1) * 4;
        *(float4*)&sh_probs[r][c4] =
            *(const float4*)(g_probs + (size_t)(mb * 128 + r) * EE + c4);
    }

    float acc[16][4];
    #pragma unroll
    for (int i = 0; i < 16; i++)
        #pragma unroll
        for (int j = 0; j < 4; j++) acc[i][j] = 0.0f;

    #pragma unroll
    for (int l = 0; l < 4; l++) {
        int lin = tid + 256 * l;
        int row = lin >> 3, ch = (lin & 7) * 8;
        cp_async16(Ah + row * ASH_STRIDE + ch, arow + (size_t)row * DD + ch);
        int kk = lin >> 5, c4 = (lin & 31) * 4;
        cp_async16(Bs2 + kk * BS2_STRIDE + c4,
                   g_wdt2 + (size_t)kk * N1 + nb * 128 + c4);
    }
    CP_COMMIT();

    const int NIT = DD / 64;
    for (int it = 0; it < NIT; it++) {
        int buf = it & 1;
        if (it + 1 < NIT) {
            int kb = (it + 1) * 64;
            int nbuf = buf ^ 1;
            #pragma unroll
            for (int l = 0; l < 4; l++) {
                int lin = tid + 256 * l;
                int row = lin >> 3, ch = (lin & 7) * 8;
                cp_async16(Ah + nbuf * ASH_BUF + row * ASH_STRIDE + ch,
                           arow + (size_t)row * DD + kb + ch);
                int kk = lin >> 5, c4 = (lin & 31) * 4;
                cp_async16(Bs2 + nbuf * BS2_BUF + kk * BS2_STRIDE + c4,
                           g_wdt2 + (size_t)(kb / 2 + kk) * N1 + nb * 128 + c4);
            }
            CP_COMMIT();
            CP_WAIT1();
        } else {
            CP_WAIT0();
        }
        __syncthreads();
        const __half* Ab = Ah + buf * ASH_BUF;
        const uint32_t* Bb = Bs2 + buf * BS2_BUF;
        #pragma unroll
        for (int ks = 0; ks < 4; ks++) {
            int k0 = ks * 16, k20 = ks * 8;
            uint32_t bfr[4][2];
            #pragma unroll
            for (int nf = 0; nf < 4; nf++) {
                int n0 = wn * 32 + nf * 8;
                bfr[nf][0] = Bb[(k20 + t) * BS2_STRIDE + n0 + g];
                bfr[nf][1] = Bb[(k20 + 4 + t) * BS2_STRIDE + n0 + g];
            }
            #pragma unroll
            for (int mf = 0; mf < 4; mf++) {
                int m0 = wm * 64 + mf * 16;
                uint32_t a0 = *(const uint32_t*)(Ab + (m0 + g) * ASH_STRIDE + k0 + 2 * t);
                uint32_t a1 = *(const uint32_t*)(Ab + (m0 + g + 8) * ASH_STRIDE + k0 + 2 * t);
                uint32_t a2 = *(const uint32_t*)(Ab + (m0 + g) * ASH_STRIDE + k0 + 8 + 2 * t);
                uint32_t a3 = *(const uint32_t*)(Ab + (m0 + g + 8) * ASH_STRIDE + k0 + 8 + 2 * t);
                #pragma unroll
                for (int nf = 0; nf < 4; nf++)
                    mma_f16(acc[mf * 4 + nf], a0, a1, a2, a3, bfr[nf][0], bfr[nf][1]);
            }
        }
        __syncthreads();
    }
    #pragma unroll
    for (int mf = 0; mf < 4; mf++) {
        #pragma unroll
        for (int nf = 0; nf < 4; nf++) {
            float* c = acc[mf * 4 + nf];
            int cl = wn * 32 + nf * 8 + 2 * t;
            int ncol = nb * 128 + cl;
            int e = ncol / CC;
            #pragma unroll
            for (int h = 0; h < 2; h++) {
                int r = wm * 64 + mf * 16 + g + h * 8;
                float p = sh_probs[r][e];
                float v0 = c[h * 2], v1 = c[h * 2 + 1];
                float g0 = 0.5f * v0 * (1.0f + erff(v0 * 0.70710678118654752f)) * p;
                float g1 = 0.5f * v1 * (1.0f + erff(v1 * 0.70710678118654752f)) * p;
                __half2 hv = __floats2half2_rn(g0, g1);
                *(uint32_t*)(g_midh + (size_t)(mb * 128 + r) * N1 + ncol) = *(uint32_t*)&hv;
            }
        }
    }
}

// ---------------- up GEMM (fp16 mma, BK=64 double-buffered) ----------------
__global__ __launch_bounds__(256, 2) void up_kernel(const float* __restrict__ x,
                                                    const float* __restrict__ alphap,
                                                    float* __restrict__ out) {
    extern __shared__ char smc[];
    __half* Ah = (__half*)smc;
    uint32_t* Bs2 = (uint32_t*)(smc + 2 * ASH_BUF * 2);
    int tid = threadIdx.x;
    int lane = tid & 31, wid = tid >> 5;
    int wm = wid & 1, wn = wid >> 1;
    int g = lane >> 2, t = lane & 3;
    int mb = blockIdx.y, nb = blockIdx.x;
    const __half* amid = g_midh + (size_t)mb * 128 * N1;

    float acc[16][4];
    #pragma unroll
    for (int i = 0; i < 16; i++)
        #pragma unroll
        for (int j = 0; j < 4; j++) acc[i][j] = 0.0f;

    #pragma unroll
    for (int l = 0; l < 4; l++) {
        int lin = tid + 256 * l;
        int row = lin >> 3, ch = (lin & 7) * 8;
        cp_async16(Ah + row * ASH_STRIDE + ch, amid + (size_t)row * N1 + ch);
        int kk = lin >> 5, c4 = (lin & 31) * 4;
        cp_async16(Bs2 + kk * BS2_STRIDE + c4,
                   g_wut2 + (size_t)kk * DD + nb * 128 + c4);
    }
    CP_COMMIT();

    const int NIT = N1 / 64;
    for (int it = 0; it < NIT; it++) {
        int buf = it & 1;
        if (it + 1 < NIT) {
            int kb = (it + 1) * 64;
            int nbuf = buf ^ 1;
            #pragma unroll
            for (int l = 0; l < 4; l++) {
                int lin = tid + 256 * l;
                int row = lin >> 3, ch = (lin & 7) * 8;
                cp_async16(Ah + nbuf * ASH_BUF + row * ASH_STRIDE + ch,
                           amid + (size_t)row * N1 + kb + ch);
                int kk = lin >> 5, c4 = (lin & 31) * 4;
                cp_async16(Bs2 + nbuf * BS2_BUF + kk * BS2_STRIDE + c4,
                           g_wut2 + (size_t)(kb / 2 + kk) * DD + nb * 128 + c4);
            }
            CP_COMMIT();
            CP_WAIT1();
        } else {
            CP_WAIT0();
        }
        __syncthreads();
        const __half* Ab = Ah + buf * ASH_BUF;
        const uint32_t* Bb = Bs2 + buf * BS2_BUF;
        #pragma unroll
        for (int ks = 0; ks < 4; ks++) {
            int k0 = ks * 16, k20 = ks * 8;
            uint32_t bfr[4][2];
            #pragma unroll
            for (int nf = 0; nf < 4; nf++) {
                int n0 = wn * 32 + nf * 8;
                bfr[nf][0] = Bb[(k20 + t) * BS2_STRIDE + n0 + g];
                bfr[nf][1] = Bb[(k20 + 4 + t) * BS2_STRIDE + n0 + g];
            }
            #pragma unroll
            for (int mf = 0; mf < 4; mf++) {
                int m0 = wm * 64 + mf * 16;
                uint32_t a0 = *(const uint32_t*)(Ab + (m0 + g) * ASH_STRIDE + k0 + 2 * t);
                uint32_t a1 = *(const uint32_t*)(Ab + (m0 + g + 8) * ASH_STRIDE + k0 + 2 * t);
                uint32_t a2 = *(const uint32_t*)(Ab + (m0 + g) * ASH_STRIDE + k0 + 8 + 2 * t);
                uint32_t a3 = *(const uint32_t*)(Ab + (m0 + g + 8) * ASH_STRIDE + k0 + 8 + 2 * t);
                #pragma unroll
                for (int nf = 0; nf < 4; nf++)
                    mma_f16(acc[mf * 4 + nf], a0, a1, a2, a3, bfr[nf][0], bfr[nf][1]);
            }
        }
        __syncthreads();
    }
    float alpha = *alphap;
    #pragma unroll
    for (int mf = 0; mf < 4; mf++) {
        #pragma unroll
        for (int nf = 0; nf < 4; nf++) {
            float* c = acc[mf * 4 + nf];
            int cl = wn * 32 + nf * 8 + 2 * t;
            int ncol = nb * 128 + cl;
            #pragma unroll
            for (int h = 0; h < 2; h++) {
                int r = wm * 64 + mf * 16 + g + h * 8;
                int gi = mb * 128 + r;
                int b = gi >> 10;
                int tt = (gi & 1023) + 1;
                size_t ro = ((size_t)b * TT + tt) * DD + ncol;
                float2 hx = *(const float2*)(x + ro);
                *(float2*)(out + ro) = make_float2(fmaf(alpha, c[h * 2], hx.x),
                                                   fmaf(alpha, c[h * 2 + 1], hx.y));
            }
        }
    }
}

// ---------------- launch ----------------
extern "C" void kernel_launch(void* const* d_in, const int* in_sizes, int n_in,
                              void* d_out, int out_size) {
    const float* x     = (const float*)d_in[0];
    const float* Q     = (const float*)d_in[1];
    const float* P     = (const float*)d_in[2];
    const float* gamma = (const float*)d_in[3];
    const float* masks = (const float*)d_in[4];
    const float* bias  = (const float*)d_in[5];
    const float* Wd    = (const float*)d_in[6];
    const float* Wu    = (const float*)d_in[7];
    const float* alpha = (const float*)d_in[8];
    float* out = (float*)d_out;

    cudaFuncSetAttribute(router_kernel,
                         cudaFuncAttributeMaxDynamicSharedMemorySize, ROUTER_DYN_SMEM);
    cudaFuncSetAttribute(down_kernel,
                         cudaFuncAttributeMaxDynamicSharedMemorySize, GEMM_DYN_SMEM);
    cudaFuncSetAttribute(up_kernel,
                         cudaFuncAttributeMaxDynamicSharedMemorySize, GEMM_DYN_SMEM);

    prep_kernel<<<2048, 256>>>(x, Wd, Wu, Q, out);
    router_kernel<<<256, 256, ROUTER_DYN_SMEM>>>(gamma, masks, bias, Q, P);
    down_kernel<<<dim3(N1 / 128, NTOK / 128), 256, GEMM_DYN_SMEM>>>();
    up_kernel<<<dim3(DD / 128, NTOK / 128), 256, GEMM_DYN_SMEM>>>(x, alpha, out);
    finalize_kernel<<<1, 32>>>(out);
}